// round 12
// baseline (speedup 1.0000x reference)
#include <cuda_runtime.h>
#include <math.h>
#include <stdint.h>

#define N_NODES 50000
#define N_EDGES 800000
#define IN_CH   128
#define OUT_CH  64
#define BN_EPS  1e-5f

// ---------------- scratch (no allocation allowed) ----------------
__device__ float g_h[N_NODES * OUT_CH];      // x @ W
__device__ float g_agg[N_NODES * OUT_CH];    // aggregated messages (edges only)
__device__ int   g_deg[N_NODES];
__device__ float g_dinv[N_NODES];
__device__ float g_sum[OUT_CH];
__device__ float g_sumsq[OUT_CH];
__device__ int   g_eidx[2 * N_EDGES];        // decoded int32 edges (src then dst)
__device__ int   g_is64;
__device__ int   g_count;                    // act_bn grid-sync counter
__device__ volatile int g_flag;              // act_bn grid-sync flag

// ---------------- packed f32x2 FFMA ----------------
__device__ __forceinline__ void ffma2(uint64_t& d, uint64_t a, uint64_t b) {
    asm("fma.rn.f32x2 %0, %1, %2, %0;" : "+l"(d) : "l"(a), "l"(b));
}
union F4U2 { float4 f; struct { uint64_t lo, hi; } u; };
union U2F2 { uint64_t u; struct { float lo, hi; } f; };

// ---------------- fused init + dtype sniff + sync reset ----------------
// int64 edges (values < 50000) have every odd 32-bit word zero.
__global__ void k_init_sniff(const unsigned int* __restrict__ w) {
    int i = blockIdx.x * blockDim.x + threadIdx.x;
    if (i < N_NODES) g_deg[i] = 1;                 // self loop
    if (i < OUT_CH) { g_sum[i] = 0.f; g_sumsq[i] = 0.f; }
    if (i == 0) {
        g_count = 0; g_flag = 0;
        int odd_zero = 1;
        #pragma unroll
        for (int j = 0; j < 16; j++)
            if (w[2 * j + 1] != 0u) odd_zero = 0;
        g_is64 = odd_zero;
    }
}

// ---------------- fused decode + in-degree ----------------
__global__ void k_decode_deg(const unsigned int* __restrict__ w) {
    int i = blockIdx.x * blockDim.x + threadIdx.x;
    if (i >= 2 * N_EDGES) return;
    int is64 = g_is64;
    int v = (int)(is64 ? w[2 * (size_t)i] : w[i]);
    g_eidx[i] = v;
    if (i >= N_EDGES) atomicAdd(&g_deg[v], 1);     // dst half
}

__global__ void k_dinv() {
    int i = blockIdx.x * blockDim.x + threadIdx.x;
    if (i < N_NODES) g_dinv[i] = rsqrtf((float)g_deg[i]);
}

// ---------------- GEMM: h[N,64] = x[N,128] @ W[128,64], FFMA2 ----------------
// 32-row tile (64 KB smem total -> 3 CTAs/SM), 256 threads,
// 2 rows x 4 cols per thread (cols as 2 f32x2 pairs).
// A stored duplicated ({v,v} per element) so the broadcast operand is one LDS.64.
// Also zeroes g_agg rows (scatter accumulates into it later).
#define TILE_M 32
#define SMEM_A_FLOATS (TILE_M * IN_CH * 2)               /* 8192 floats = 32 KB */
#define SMEM_TOT ((SMEM_A_FLOATS + IN_CH * OUT_CH) * 4)  /* + Ws 32 KB = 64 KB */

__global__ void __launch_bounds__(256) k_gemm(const float* __restrict__ x,
                                              const float* __restrict__ W) {
    extern __shared__ float sm[];
    float* As2 = sm;                       // [32][128][2] duplicated
    float* Ws  = sm + SMEM_A_FLOATS;       // [128][64]
    const int tid  = threadIdx.x;
    const int row0 = blockIdx.x * TILE_M;

    // load W (8192 floats) as float4
    for (int i = tid; i < (IN_CH * OUT_CH) / 4; i += 256)
        ((float4*)Ws)[i] = ((const float4*)W)[i];

    // load x tile (32 x 128) as float4; store duplicated; zero-fill OOB rows
    for (int i = tid; i < (TILE_M * IN_CH) / 4; i += 256) {
        int lin = i * 4;
        int r = lin >> 7, c = lin & 127;
        int gr = row0 + r;
        float4 v = make_float4(0.f, 0.f, 0.f, 0.f);
        if (gr < N_NODES) v = *((const float4*)(x + (size_t)gr * IN_CH + c));
        float* p = As2 + ((size_t)r * IN_CH + c) * 2;
        *((float4*)p)     = make_float4(v.x, v.x, v.y, v.y);
        *((float4*)(p+4)) = make_float4(v.z, v.z, v.w, v.w);
    }
    __syncthreads();

    const int ty = tid >> 4;       // 0..15 -> rows ty*2, ty*2+1
    const int tx = tid & 15;       // 0..15 -> cols tx*4..tx*4+3
    uint64_t acc[2][2] = {};       // 2 rows x (2 f32x2 col-pairs)

    const float* pa0 = As2 + (ty * 2 + 0) * (IN_CH * 2);
    const float* pa1 = As2 + (ty * 2 + 1) * (IN_CH * 2);
    const float* pb  = Ws + tx * 4;

    #pragma unroll 8
    for (int k = 0; k < IN_CH; k++) {
        uint64_t a0 = *(const uint64_t*)(pa0 + 2 * k);
        uint64_t a1 = *(const uint64_t*)(pa1 + 2 * k);
        F4U2 b; b.f = *(const float4*)(pb + k * OUT_CH);
        ffma2(acc[0][0], a0, b.u.lo); ffma2(acc[0][1], a0, b.u.hi);
        ffma2(acc[1][0], a1, b.u.lo); ffma2(acc[1][1], a1, b.u.hi);
    }

    const float4 z = make_float4(0.f, 0.f, 0.f, 0.f);
    #pragma unroll
    for (int i = 0; i < 2; i++) {
        int r = row0 + ty * 2 + i;
        if (r < N_NODES) {
            U2F2 lo, hi; lo.u = acc[i][0]; hi.u = acc[i][1];
            *((float4*)&g_h[(size_t)r * OUT_CH + tx * 4]) =
                make_float4(lo.f.lo, lo.f.hi, hi.f.lo, hi.f.hi);
            *((float4*)&g_agg[(size_t)r * OUT_CH + tx * 4]) = z;
        }
    }
}

// ---------------- edge scatter: 16 threads / edge, v4 red ----------------
__global__ void __launch_bounds__(256) k_scatter() {
    long long t = (long long)blockIdx.x * blockDim.x + threadIdx.x;
    if (t >= (long long)N_EDGES * 16) return;
    int e = (int)(t >> 4), q = (int)(t & 15);
    int s = g_eidx[e];
    int d = g_eidx[N_EDGES + e];
    float norm = g_dinv[s] * g_dinv[d];
    float4 v = *((const float4*)&g_h[(size_t)s * OUT_CH + q * 4]);
    float* p = &g_agg[(size_t)d * OUT_CH + q * 4];
    asm volatile("red.global.add.v4.f32 [%0], {%1,%2,%3,%4};"
                 :: "l"(p), "f"(v.x * norm), "f"(v.y * norm),
                    "f"(v.z * norm), "f"(v.w * norm)
                 : "memory");
}

// ---- fused act + batchnorm, persistent grid with counter/flag sync ----
// out = BN(tanh(agg + dinv^2*h + bias)); values held in registers between phases.
// Grid = 296 (2 blocks/SM guaranteed resident -> spin is deadlock-free).
#define AB_GRID 296
#define AB_STRIDE (AB_GRID * 256)          /* 75776, multiple of 16 */
#define AB_ITERS 11                        /* ceil(800000 / 75776) */

__global__ void __launch_bounds__(256, 2) k_act_bn(const float* __restrict__ bias,
                                                   const float* __restrict__ gamma,
                                                   const float* __restrict__ beta,
                                                   float* __restrict__ out) {
    const int tid = threadIdx.x;
    const int cg = tid & 15;
    const float4 b4 = ((const float4*)bias)[cg];
    const int total4 = N_NODES * 16;
    const int base = blockIdx.x * 256 + tid;

    float4 vals[AB_ITERS];
    float4 s  = make_float4(0.f, 0.f, 0.f, 0.f);
    float4 s2 = make_float4(0.f, 0.f, 0.f, 0.f);

    // phase 1: tanh + stats, values cached in registers
    {
        int i = base;
        #pragma unroll
        for (int j = 0; j < AB_ITERS; j++, i += AB_STRIDE) {
            if (i < total4) {
                int n = i >> 4;
                float di = g_dinv[n];
                float sl = di * di;
                float4 a = ((const float4*)g_agg)[i];
                float4 h = ((const float4*)g_h)[i];
                float4 v;
                v.x = tanhf(a.x + sl * h.x + b4.x);
                v.y = tanhf(a.y + sl * h.y + b4.y);
                v.z = tanhf(a.z + sl * h.z + b4.z);
                v.w = tanhf(a.w + sl * h.w + b4.w);
                vals[j] = v;
                s.x += v.x; s.y += v.y; s.z += v.z; s.w += v.w;
                s2.x += v.x * v.x; s2.y += v.y * v.y; s2.z += v.z * v.z; s2.w += v.w * v.w;
            }
        }
    }

    // block reduce + global atomics
    __shared__ float4 sh[256];
    sh[tid] = s; __syncthreads();
    if (tid < 16) {
        float4 acc = sh[tid];
        #pragma unroll
        for (int j = 1; j < 16; j++) {
            float4 o = sh[tid + 16 * j];
            acc.x += o.x; acc.y += o.y; acc.z += o.z; acc.w += o.w;
        }
        atomicAdd(&g_sum[cg * 4 + 0], acc.x);
        atomicAdd(&g_sum[cg * 4 + 1], acc.y);
        atomicAdd(&g_sum[cg * 4 + 2], acc.z);
        atomicAdd(&g_sum[cg * 4 + 3], acc.w);
    }
    __syncthreads();
    sh[tid] = s2; __syncthreads();
    if (tid < 16) {
        float4 acc = sh[tid];
        #pragma unroll
        for (int j = 1; j < 16; j++) {
            float4 o = sh[tid + 16 * j];
            acc.x += o.x; acc.y += o.y; acc.z += o.z; acc.w += o.w;
        }
        atomicAdd(&g_sumsq[cg * 4 + 0], acc.x);
        atomicAdd(&g_sumsq[cg * 4 + 1], acc.y);
        atomicAdd(&g_sumsq[cg * 4 + 2], acc.z);
        atomicAdd(&g_sumsq[cg * 4 + 3], acc.w);
    }
    __syncthreads();

    // grid sync: last block releases the flag
    if (tid == 0) {
        __threadfence();
        int o = atomicAdd(&g_count, 1);
        if (o == AB_GRID - 1) atomicExch((int*)&g_flag, 1);
        while (g_flag == 0) __nanosleep(64);
    }
    __syncthreads();
    __threadfence();

    // phase 2: read final sums via L2, apply BN from registers
    float4 sc, sf;
    {
        const float invN = 1.0f / (float)N_NODES;
        float4 su = __ldcg(&((const float4*)g_sum)[cg]);
        float4 sq = __ldcg(&((const float4*)g_sumsq)[cg]);
        float4 g4 = ((const float4*)gamma)[cg];
        float4 be4 = ((const float4*)beta)[cg];
        float mx = su.x * invN, my = su.y * invN, mz = su.z * invN, mw = su.w * invN;
        sc.x = g4.x * rsqrtf(sq.x * invN - mx * mx + BN_EPS);
        sc.y = g4.y * rsqrtf(sq.y * invN - my * my + BN_EPS);
        sc.z = g4.z * rsqrtf(sq.z * invN - mz * mz + BN_EPS);
        sc.w = g4.w * rsqrtf(sq.w * invN - mw * mw + BN_EPS);
        sf.x = be4.x - mx * sc.x;
        sf.y = be4.y - my * sc.y;
        sf.z = be4.z - mz * sc.z;
        sf.w = be4.w - mw * sc.w;
    }
    {
        int i = base;
        #pragma unroll
        for (int j = 0; j < AB_ITERS; j++, i += AB_STRIDE) {
            if (i < total4) {
                float4 v = vals[j];
                v.x = v.x * sc.x + sf.x;
                v.y = v.y * sc.y + sf.y;
                v.z = v.z * sc.z + sf.z;
                v.w = v.w * sc.w + sf.w;
                ((float4*)out)[i] = v;
            }
        }
    }
}

// ---------------- streams/events (created once; no device memory) ----------------
static struct SideStream {
    cudaStream_t s;
    cudaEvent_t fork_ev, join_ev;
    SideStream() {
        cudaStreamCreateWithFlags(&s, cudaStreamNonBlocking);
        cudaEventCreateWithFlags(&fork_ev, cudaEventDisableTiming);
        cudaEventCreateWithFlags(&join_ev, cudaEventDisableTiming);
        cudaFuncSetAttribute(k_gemm, cudaFuncAttributeMaxDynamicSharedMemorySize, SMEM_TOT);
    }
} g_ss;

// ---------------- launch ----------------
extern "C" void kernel_launch(void* const* d_in, const int* in_sizes, int n_in,
                              void* d_out, int out_size) {
    const float*        x     = (const float*)d_in[0];
    const unsigned int* ei    = (const unsigned int*)d_in[1];  // int32 or int64, sniffed
    const float*        W     = (const float*)d_in[2];
    const float*        bias  = (const float*)d_in[3];
    const float*        gamma = (const float*)d_in[4];
    const float*        beta  = (const float*)d_in[5];
    float*              out   = (float*)d_out;

    static bool attr_done = false;
    if (!attr_done) {   // first call is outside graph capture
        cudaFuncSetAttribute(k_gemm, cudaFuncAttributeMaxDynamicSharedMemorySize, SMEM_TOT);
        attr_done = true;
    }

    // fork: edge chain on side stream, overlapped with GEMM on main stream
    cudaEventRecord(g_ss.fork_ev, 0);
    cudaStreamWaitEvent(g_ss.s, g_ss.fork_ev, 0);

    k_init_sniff<<<(N_NODES + 255) / 256, 256, 0, g_ss.s>>>(ei);
    k_decode_deg<<<(2 * N_EDGES + 255) / 256, 256, 0, g_ss.s>>>(ei);
    k_dinv<<<(N_NODES + 255) / 256, 256, 0, g_ss.s>>>();
    cudaEventRecord(g_ss.join_ev, g_ss.s);

    k_gemm<<<(N_NODES + TILE_M - 1) / TILE_M, 256, SMEM_TOT>>>(x, W);

    // join, then scatter + fused act/bn on main stream
    cudaStreamWaitEvent(0, g_ss.join_ev, 0);
    k_scatter<<<(int)(((long long)N_EDGES * 16 + 255) / 256), 256>>>();
    k_act_bn<<<AB_GRID, 256>>>(bias, gamma, beta, out);
}

// round 13
// speedup vs baseline: 1.0849x; 1.0849x over previous
#include <cuda_runtime.h>
#include <math.h>
#include <stdint.h>

#define N_NODES 50000
#define N_EDGES 800000
#define IN_CH   128
#define OUT_CH  64
#define BN_EPS  1e-5f

// ---------------- scratch (no allocation allowed) ----------------
__device__ float g_h[N_NODES * OUT_CH];      // x @ W
__device__ float g_agg[N_NODES * OUT_CH];    // aggregated messages (edges only)
__device__ int   g_deg[N_NODES];
__device__ float g_dinv[N_NODES];
__device__ float g_sum[OUT_CH];
__device__ float g_sumsq[OUT_CH];
__device__ int   g_eidx[2 * N_EDGES];        // decoded int32 edges (src then dst)
__device__ int   g_is64;
__device__ int   g_count;                    // act_bn grid-sync counter
__device__ volatile int g_flag;              // act_bn grid-sync flag

// ---------------- packed f32x2 FFMA ----------------
__device__ __forceinline__ void ffma2(unsigned long long& d, unsigned long long a,
                                      unsigned long long b) {
    asm("fma.rn.f32x2 %0, %1, %2, %0;" : "+l"(d) : "l"(a), "l"(b));
}
union U2F2 { unsigned long long u; struct { float lo, hi; } f; };

// ---------------- fused init + dtype sniff + sync reset ----------------
// int64 edges (values < 50000) have every odd 32-bit word zero.
__global__ void k_init_sniff(const unsigned int* __restrict__ w) {
    int i = blockIdx.x * blockDim.x + threadIdx.x;
    if (i < N_NODES) g_deg[i] = 1;                 // self loop
    if (i < OUT_CH) { g_sum[i] = 0.f; g_sumsq[i] = 0.f; }
    if (i == 0) {
        g_count = 0; g_flag = 0;
        int odd_zero = 1;
        #pragma unroll
        for (int j = 0; j < 16; j++)
            if (w[2 * j + 1] != 0u) odd_zero = 0;
        g_is64 = odd_zero;
    }
}

// ---------------- fused decode + in-degree ----------------
__global__ void k_decode_deg(const unsigned int* __restrict__ w) {
    int i = blockIdx.x * blockDim.x + threadIdx.x;
    if (i >= 2 * N_EDGES) return;
    int is64 = g_is64;
    int v = (int)(is64 ? w[2 * (size_t)i] : w[i]);
    g_eidx[i] = v;
    if (i >= N_EDGES) atomicAdd(&g_deg[v], 1);     // dst half
}

__global__ void k_dinv() {
    int i = blockIdx.x * blockDim.x + threadIdx.x;
    if (i < N_NODES) g_dinv[i] = rsqrtf((float)g_deg[i]);
}

// ================= GEMM: h[N,64] = x[N,128] @ W[128,64] =================
// Broadcast-B FFMA2 design:
//   lane = row. Thread computes 1 row x 32 cols (tid>>7 selects col half).
//   W held transposed+paired in smem: Wt2[c][kp] = {W[2kp][c], W[2kp+1][c]}.
//   All 32 lanes read the SAME Wt2 word -> smem broadcast (1 transaction).
//   A row read as natural {A[k],A[k+1]} u64 pairs from padded smem tile.
//   acc_c accumulates even/odd-k partial sums; final h = lo + hi.
// Also zeroes g_agg rows (scatter accumulates into it later).
#define TILE_M    128
#define AS_STRIDE 132                       /* floats; %32==4 -> conflict-free LDS.128 */
#define WT_STRIDE 66                        /* u64 per Wt2 row */
#define AS_BYTES  (TILE_M * AS_STRIDE * 4)  /* 67584 */
#define SMEM_TOT  (AS_BYTES + 64 * WT_STRIDE * 8)  /* + 33792 = 101376 */

__global__ void __launch_bounds__(256, 2) k_gemm(const float* __restrict__ x,
                                                 const float* __restrict__ W) {
    extern __shared__ char smraw[];
    float* As = (float*)smraw;                                  // [128][132]
    unsigned long long* Wt2 = (unsigned long long*)(smraw + AS_BYTES); // [64][66]
    const int tid  = threadIdx.x;
    const int row0 = blockIdx.x * TILE_M;

    // stage A tile: coalesced LDG.128 (warp covers one row), conflict-free STS.128
    #pragma unroll
    for (int i = 0; i < 16; i++) {
        int idx4 = tid + i * 256;            // 4096 float4s = 128 rows x 32
        int r = idx4 >> 5, c4 = idx4 & 31;
        int gr = row0 + r;
        float4 v = make_float4(0.f, 0.f, 0.f, 0.f);
        if (gr < N_NODES) v = *(const float4*)(x + (size_t)gr * IN_CH + c4 * 4);
        *(float4*)&As[r * AS_STRIDE + c4 * 4] = v;
    }
    // stage Wt2: transpose + pair W. Coalesced LDG.32 pairs, STS.64.
    #pragma unroll
    for (int i = 0; i < 16; i++) {
        int e = tid + i * 256;               // 4096 entries = 64 c x 64 kp
        int c = e & 63, kp = e >> 6;
        float lo = W[(size_t)(2 * kp) * OUT_CH + c];
        float hi = W[(size_t)(2 * kp + 1) * OUT_CH + c];
        unsigned long long p;
        asm("mov.b64 %0, {%1,%2};" : "=l"(p) : "f"(lo), "f"(hi));
        Wt2[c * WT_STRIDE + kp] = p;
    }
    __syncthreads();

    const int r  = tid & 127;
    const int ch = tid >> 7;                 // col half: 0 -> cols 0..31, 1 -> 32..63
    unsigned long long acc[32];
    #pragma unroll
    for (int c = 0; c < 32; c++) acc[c] = 0ULL;

    const unsigned long long* wbase = Wt2 + (ch * 32) * WT_STRIDE;
    const float* arow = As + r * AS_STRIDE;

    #pragma unroll 1
    for (int kc = 0; kc < 4; kc++) {         // chunks of 32 k (16 kpairs)
        ulonglong2 a2[8];                    // 16 u64 = {A[k],A[k+1]} pairs
        #pragma unroll
        for (int j = 0; j < 8; j++)
            a2[j] = *(const ulonglong2*)(arow + kc * 32 + j * 4);
        #pragma unroll
        for (int c = 0; c < 32; c++) {
            const unsigned long long* wrow = wbase + c * WT_STRIDE + kc * 16;
            #pragma unroll
            for (int q = 0; q < 8; q++) {
                ulonglong2 b2 = *(const ulonglong2*)(wrow + q * 2);  // broadcast
                ffma2(acc[c], a2[q].x, b2.x);
                ffma2(acc[c], a2[q].y, b2.y);
            }
        }
    }

    int gr = row0 + r;
    if (gr < N_NODES) {
        float4* ph = (float4*)&g_h[(size_t)gr * OUT_CH + ch * 32];
        float4* pa = (float4*)&g_agg[(size_t)gr * OUT_CH + ch * 32];
        const float4 z = make_float4(0.f, 0.f, 0.f, 0.f);
        #pragma unroll
        for (int j = 0; j < 8; j++) {
            U2F2 u0, u1, u2, u3;
            u0.u = acc[4 * j + 0]; u1.u = acc[4 * j + 1];
            u2.u = acc[4 * j + 2]; u3.u = acc[4 * j + 3];
            ph[j] = make_float4(u0.f.lo + u0.f.hi, u1.f.lo + u1.f.hi,
                                u2.f.lo + u2.f.hi, u3.f.lo + u3.f.hi);
            pa[j] = z;
        }
    }
}

// ---------------- edge scatter: 16 threads / edge, v4 red ----------------
__global__ void __launch_bounds__(256) k_scatter() {
    long long t = (long long)blockIdx.x * blockDim.x + threadIdx.x;
    if (t >= (long long)N_EDGES * 16) return;
    int e = (int)(t >> 4), q = (int)(t & 15);
    int s = g_eidx[e];
    int d = g_eidx[N_EDGES + e];
    float norm = g_dinv[s] * g_dinv[d];
    float4 v = *((const float4*)&g_h[(size_t)s * OUT_CH + q * 4]);
    float* p = &g_agg[(size_t)d * OUT_CH + q * 4];
    asm volatile("red.global.add.v4.f32 [%0], {%1,%2,%3,%4};"
                 :: "l"(p), "f"(v.x * norm), "f"(v.y * norm),
                    "f"(v.z * norm), "f"(v.w * norm)
                 : "memory");
}

// ---- fused act + batchnorm, persistent grid with counter/flag sync ----
#define AB_GRID 296
#define AB_STRIDE (AB_GRID * 256)          /* 75776, multiple of 16 */
#define AB_ITERS 11                        /* ceil(800000 / 75776) */

__global__ void __launch_bounds__(256, 2) k_act_bn(const float* __restrict__ bias,
                                                   const float* __restrict__ gamma,
                                                   const float* __restrict__ beta,
                                                   float* __restrict__ out) {
    const int tid = threadIdx.x;
    const int cg = tid & 15;
    const float4 b4 = ((const float4*)bias)[cg];
    const int total4 = N_NODES * 16;
    const int base = blockIdx.x * 256 + tid;

    float4 vals[AB_ITERS];
    float4 s  = make_float4(0.f, 0.f, 0.f, 0.f);
    float4 s2 = make_float4(0.f, 0.f, 0.f, 0.f);

    {
        int i = base;
        #pragma unroll
        for (int j = 0; j < AB_ITERS; j++, i += AB_STRIDE) {
            if (i < total4) {
                int n = i >> 4;
                float di = g_dinv[n];
                float sl = di * di;
                float4 a = ((const float4*)g_agg)[i];
                float4 h = ((const float4*)g_h)[i];
                float4 v;
                v.x = tanhf(a.x + sl * h.x + b4.x);
                v.y = tanhf(a.y + sl * h.y + b4.y);
                v.z = tanhf(a.z + sl * h.z + b4.z);
                v.w = tanhf(a.w + sl * h.w + b4.w);
                vals[j] = v;
                s.x += v.x; s.y += v.y; s.z += v.z; s.w += v.w;
                s2.x += v.x * v.x; s2.y += v.y * v.y; s2.z += v.z * v.z; s2.w += v.w * v.w;
            }
        }
    }

    __shared__ float4 sh[256];
    sh[tid] = s; __syncthreads();
    if (tid < 16) {
        float4 acc = sh[tid];
        #pragma unroll
        for (int j = 1; j < 16; j++) {
            float4 o = sh[tid + 16 * j];
            acc.x += o.x; acc.y += o.y; acc.z += o.z; acc.w += o.w;
        }
        atomicAdd(&g_sum[cg * 4 + 0], acc.x);
        atomicAdd(&g_sum[cg * 4 + 1], acc.y);
        atomicAdd(&g_sum[cg * 4 + 2], acc.z);
        atomicAdd(&g_sum[cg * 4 + 3], acc.w);
    }
    __syncthreads();
    sh[tid] = s2; __syncthreads();
    if (tid < 16) {
        float4 acc = sh[tid];
        #pragma unroll
        for (int j = 1; j < 16; j++) {
            float4 o = sh[tid + 16 * j];
            acc.x += o.x; acc.y += o.y; acc.z += o.z; acc.w += o.w;
        }
        atomicAdd(&g_sumsq[cg * 4 + 0], acc.x);
        atomicAdd(&g_sumsq[cg * 4 + 1], acc.y);
        atomicAdd(&g_sumsq[cg * 4 + 2], acc.z);
        atomicAdd(&g_sumsq[cg * 4 + 3], acc.w);
    }
    __syncthreads();

    if (tid == 0) {
        __threadfence();
        int o = atomicAdd(&g_count, 1);
        if (o == AB_GRID - 1) atomicExch((int*)&g_flag, 1);
        while (g_flag == 0) __nanosleep(64);
    }
    __syncthreads();
    __threadfence();

    float4 sc, sf;
    {
        const float invN = 1.0f / (float)N_NODES;
        float4 su = __ldcg(&((const float4*)g_sum)[cg]);
        float4 sq = __ldcg(&((const float4*)g_sumsq)[cg]);
        float4 g4 = ((const float4*)gamma)[cg];
        float4 be4 = ((const float4*)beta)[cg];
        float mx = su.x * invN, my = su.y * invN, mz = su.z * invN, mw = su.w * invN;
        sc.x = g4.x * rsqrtf(sq.x * invN - mx * mx + BN_EPS);
        sc.y = g4.y * rsqrtf(sq.y * invN - my * my + BN_EPS);
        sc.z = g4.z * rsqrtf(sq.z * invN - mz * mz + BN_EPS);
        sc.w = g4.w * rsqrtf(sq.w * invN - mw * mw + BN_EPS);
        sf.x = be4.x - mx * sc.x;
        sf.y = be4.y - my * sc.y;
        sf.z = be4.z - mz * sc.z;
        sf.w = be4.w - mw * sc.w;
    }
    {
        int i = base;
        #pragma unroll
        for (int j = 0; j < AB_ITERS; j++, i += AB_STRIDE) {
            if (i < total4) {
                float4 v = vals[j];
                v.x = v.x * sc.x + sf.x;
                v.y = v.y * sc.y + sf.y;
                v.z = v.z * sc.z + sf.z;
                v.w = v.w * sc.w + sf.w;
                ((float4*)out)[i] = v;
            }
        }
    }
}

// ---------------- streams/events (created once; no device memory) ----------------
static struct SideStream {
    cudaStream_t s;
    cudaEvent_t fork_ev, join_ev;
    SideStream() {
        cudaStreamCreateWithFlags(&s, cudaStreamNonBlocking);
        cudaEventCreateWithFlags(&fork_ev, cudaEventDisableTiming);
        cudaEventCreateWithFlags(&join_ev, cudaEventDisableTiming);
        cudaFuncSetAttribute(k_gemm, cudaFuncAttributeMaxDynamicSharedMemorySize, SMEM_TOT);
    }
} g_ss;

// ---------------- launch ----------------
extern "C" void kernel_launch(void* const* d_in, const int* in_sizes, int n_in,
                              void* d_out, int out_size) {
    const float*        x     = (const float*)d_in[0];
    const unsigned int* ei    = (const unsigned int*)d_in[1];  // int32 or int64, sniffed
    const float*        W     = (const float*)d_in[2];
    const float*        bias  = (const float*)d_in[3];
    const float*        gamma = (const float*)d_in[4];
    const float*        beta  = (const float*)d_in[5];
    float*              out   = (float*)d_out;

    static bool attr_done = false;
    if (!attr_done) {   // first call is outside graph capture
        cudaFuncSetAttribute(k_gemm, cudaFuncAttributeMaxDynamicSharedMemorySize, SMEM_TOT);
        attr_done = true;
    }

    // fork: edge chain on side stream, overlapped with GEMM on main stream
    cudaEventRecord(g_ss.fork_ev, 0);
    cudaStreamWaitEvent(g_ss.s, g_ss.fork_ev, 0);

    k_init_sniff<<<(N_NODES + 255) / 256, 256, 0, g_ss.s>>>(ei);
    k_decode_deg<<<(2 * N_EDGES + 255) / 256, 256, 0, g_ss.s>>>(ei);
    k_dinv<<<(N_NODES + 255) / 256, 256, 0, g_ss.s>>>();
    cudaEventRecord(g_ss.join_ev, g_ss.s);

    k_gemm<<<(N_NODES + TILE_M - 1) / TILE_M, 256, SMEM_TOT>>>(x, W);

    // join, then scatter + fused act/bn on main stream
    cudaStreamWaitEvent(0, g_ss.join_ev, 0);
    k_scatter<<<(int)(((long long)N_EDGES * 16 + 255) / 256), 256>>>();
    k_act_bn<<<AB_GRID, 256>>>(bias, gamma, beta, out);
}

// round 14
// speedup vs baseline: 1.2603x; 1.1617x over previous
#include <cuda_runtime.h>
#include <math.h>
#include <stdint.h>

#define N_NODES 50000
#define N_EDGES 800000
#define IN_CH   128
#define OUT_CH  64
#define BN_EPS  1e-5f

// ---------------- scratch (no allocation allowed) ----------------
__device__ float g_h[N_NODES * OUT_CH];      // x @ W
__device__ float g_agg[N_NODES * OUT_CH];    // aggregated messages (edges only)
__device__ int   g_deg[N_NODES];
__device__ float g_dinv[N_NODES];
__device__ float g_sum[OUT_CH];
__device__ float g_sumsq[OUT_CH];
__device__ int   g_eidx[2 * N_EDGES];        // decoded int32 edges (src then dst)
__device__ int   g_is64;
__device__ int   g_count;                    // act_bn grid-sync counter
__device__ volatile int g_flag;              // act_bn grid-sync flag

// ---------------- packed f32x2 FFMA ----------------
__device__ __forceinline__ void ffma2(unsigned long long& d, unsigned long long a,
                                      unsigned long long b) {
    asm("fma.rn.f32x2 %0, %1, %2, %0;" : "+l"(d) : "l"(a), "l"(b));
}
__device__ __forceinline__ unsigned long long dup2(float a) {
    unsigned long long r;
    asm("mov.b64 %0, {%1,%1};" : "=l"(r) : "f"(a));
    return r;
}
union F4U2 { float4 f; struct { unsigned long long lo, hi; } u; };
union U2F2 { unsigned long long u; struct { float lo, hi; } f; };

// ---------------- fused init + dtype sniff + sync reset ----------------
// int64 edges (values < 50000) have every odd 32-bit word zero.
__global__ void k_init_sniff(const unsigned int* __restrict__ w) {
    int i = blockIdx.x * blockDim.x + threadIdx.x;
    if (i < N_NODES) g_deg[i] = 1;                 // self loop
    if (i < OUT_CH) { g_sum[i] = 0.f; g_sumsq[i] = 0.f; }
    if (i == 0) {
        g_count = 0; g_flag = 0;
        int odd_zero = 1;
        #pragma unroll
        for (int j = 0; j < 16; j++)
            if (w[2 * j + 1] != 0u) odd_zero = 0;
        g_is64 = odd_zero;
    }
}

// ---------------- fused decode + in-degree ----------------
__global__ void k_decode_deg(const unsigned int* __restrict__ w) {
    int i = blockIdx.x * blockDim.x + threadIdx.x;
    if (i >= 2 * N_EDGES) return;
    int is64 = g_is64;
    int v = (int)(is64 ? w[2 * (size_t)i] : w[i]);
    g_eidx[i] = v;
    if (i >= N_EDGES) atomicAdd(&g_deg[v], 1);     // dst half
}

__global__ void k_dinv() {
    int i = blockIdx.x * blockDim.x + threadIdx.x;
    if (i < N_NODES) g_dinv[i] = rsqrtf((float)g_deg[i]);
}

// ================= GEMM: h[N,64] = x[N,128] @ W[128,64] =================
// Classic 8x4 micro-tile, minimizing LDS bytes/FMA:
//   block tile 128 rows x 64 cols, 256 threads: ty=tid>>4 -> rows ty*8..+7,
//   tx=tid&15 -> cols tx*4..+3 (held as 2 f32x2 col-pairs per row).
//   Per 4-k group per warp: 8 LDS.128 (A, 4 k's each) + 4 LDS.128 (B).
//   A-dup {a,a} built by 1 mov.b64 (ALU pipe, no crossbar cost).
//   XOR swizzle (c4 ^ ((r>>3)&1), 16B granule) makes the warp's two ty-group
//   A loads hit different bank quads -> conflict-free.
// Also zeroes g_agg rows (scatter accumulates into it later).
#define TILE_M 128
#define SMEM_TOT ((128 * 128 + 128 * 64) * 4)     /* As 64 KB + Ws 32 KB = 96 KB */

__global__ void __launch_bounds__(256, 2) k_gemm(const float* __restrict__ x,
                                                 const float* __restrict__ W) {
    extern __shared__ float4 sm4[];
    float4* As4 = sm4;                 // [128][32] float4, swizzled
    float4* Ws4 = sm4 + 128 * 32;      // [128][16] float4 (row-major W)
    const int tid  = threadIdx.x;
    const int row0 = blockIdx.x * TILE_M;

    // stage A: coalesced LDG.128 (warp = one row), swizzled STS.128
    #pragma unroll
    for (int i = 0; i < 16; i++) {
        int idx4 = tid + i * 256;          // 4096 = 128 rows x 32 float4
        int r = idx4 >> 5, c4 = idx4 & 31;
        int gr = row0 + r;
        float4 v = make_float4(0.f, 0.f, 0.f, 0.f);
        if (gr < N_NODES) v = ((const float4*)(x + (size_t)gr * IN_CH))[c4];
        As4[r * 32 + (c4 ^ ((r >> 3) & 1))] = v;
    }
    // stage W: direct float4 copy (2048 float4)
    #pragma unroll
    for (int i = 0; i < 8; i++)
        Ws4[tid + i * 256] = ((const float4*)W)[tid + i * 256];
    __syncthreads();

    const int ty = tid >> 4;           // 0..15
    const int tx = tid & 15;           // 0..15
    const int sw = ty & 1;             // per-thread A swizzle bit
    unsigned long long acc[8][2] = {};
    const float4* arow = As4 + ty * 8 * 32;

    #pragma unroll 2
    for (int kg = 0; kg < 32; kg++) {  // 32 groups of 4 k
        float4 a4[8];
        #pragma unroll
        for (int i = 0; i < 8; i++)
            a4[i] = arow[i * 32 + (kg ^ sw)];
        #pragma unroll
        for (int j = 0; j < 4; j++) {
            F4U2 b; b.f = Ws4[(kg * 4 + j) * 16 + tx];
            #pragma unroll
            for (int i = 0; i < 8; i++) {
                float a = (j == 0) ? a4[i].x : (j == 1) ? a4[i].y
                         : (j == 2) ? a4[i].z : a4[i].w;
                unsigned long long aa = dup2(a);
                ffma2(acc[i][0], aa, b.u.lo);
                ffma2(acc[i][1], aa, b.u.hi);
            }
        }
    }

    const float4 z = make_float4(0.f, 0.f, 0.f, 0.f);
    #pragma unroll
    for (int i = 0; i < 8; i++) {
        int gr = row0 + ty * 8 + i;
        if (gr < N_NODES) {
            U2F2 l, h; l.u = acc[i][0]; h.u = acc[i][1];
            *(float4*)&g_h[(size_t)gr * OUT_CH + tx * 4] =
                make_float4(l.f.lo, l.f.hi, h.f.lo, h.f.hi);
            *(float4*)&g_agg[(size_t)gr * OUT_CH + tx * 4] = z;
        }
    }
}

// ---------------- edge scatter: 16 threads / edge, v4 red ----------------
__global__ void __launch_bounds__(256) k_scatter() {
    long long t = (long long)blockIdx.x * blockDim.x + threadIdx.x;
    if (t >= (long long)N_EDGES * 16) return;
    int e = (int)(t >> 4), q = (int)(t & 15);
    int s = g_eidx[e];
    int d = g_eidx[N_EDGES + e];
    float norm = g_dinv[s] * g_dinv[d];
    float4 v = *((const float4*)&g_h[(size_t)s * OUT_CH + q * 4]);
    float* p = &g_agg[(size_t)d * OUT_CH + q * 4];
    asm volatile("red.global.add.v4.f32 [%0], {%1,%2,%3,%4};"
                 :: "l"(p), "f"(v.x * norm), "f"(v.y * norm),
                    "f"(v.z * norm), "f"(v.w * norm)
                 : "memory");
}

// ---- fused act + batchnorm, persistent grid with counter/flag sync ----
#define AB_GRID 296
#define AB_STRIDE (AB_GRID * 256)          /* 75776, multiple of 16 */
#define AB_ITERS 11                        /* ceil(800000 / 75776) */

__global__ void __launch_bounds__(256, 2) k_act_bn(const float* __restrict__ bias,
                                                   const float* __restrict__ gamma,
                                                   const float* __restrict__ beta,
                                                   float* __restrict__ out) {
    const int tid = threadIdx.x;
    const int cg = tid & 15;
    const float4 b4 = ((const float4*)bias)[cg];
    const int total4 = N_NODES * 16;
    const int base = blockIdx.x * 256 + tid;

    float4 vals[AB_ITERS];
    float4 s  = make_float4(0.f, 0.f, 0.f, 0.f);
    float4 s2 = make_float4(0.f, 0.f, 0.f, 0.f);

    {
        int i = base;
        #pragma unroll
        for (int j = 0; j < AB_ITERS; j++, i += AB_STRIDE) {
            if (i < total4) {
                int n = i >> 4;
                float di = g_dinv[n];
                float sl = di * di;
                float4 a = ((const float4*)g_agg)[i];
                float4 h = ((const float4*)g_h)[i];
                float4 v;
                v.x = tanhf(a.x + sl * h.x + b4.x);
                v.y = tanhf(a.y + sl * h.y + b4.y);
                v.z = tanhf(a.z + sl * h.z + b4.z);
                v.w = tanhf(a.w + sl * h.w + b4.w);
                vals[j] = v;
                s.x += v.x; s.y += v.y; s.z += v.z; s.w += v.w;
                s2.x += v.x * v.x; s2.y += v.y * v.y; s2.z += v.z * v.z; s2.w += v.w * v.w;
            }
        }
    }

    __shared__ float4 sh[256];
    sh[tid] = s; __syncthreads();
    if (tid < 16) {
        float4 acc = sh[tid];
        #pragma unroll
        for (int j = 1; j < 16; j++) {
            float4 o = sh[tid + 16 * j];
            acc.x += o.x; acc.y += o.y; acc.z += o.z; acc.w += o.w;
        }
        atomicAdd(&g_sum[cg * 4 + 0], acc.x);
        atomicAdd(&g_sum[cg * 4 + 1], acc.y);
        atomicAdd(&g_sum[cg * 4 + 2], acc.z);
        atomicAdd(&g_sum[cg * 4 + 3], acc.w);
    }
    __syncthreads();
    sh[tid] = s2; __syncthreads();
    if (tid < 16) {
        float4 acc = sh[tid];
        #pragma unroll
        for (int j = 1; j < 16; j++) {
            float4 o = sh[tid + 16 * j];
            acc.x += o.x; acc.y += o.y; acc.z += o.z; acc.w += o.w;
        }
        atomicAdd(&g_sumsq[cg * 4 + 0], acc.x);
        atomicAdd(&g_sumsq[cg * 4 + 1], acc.y);
        atomicAdd(&g_sumsq[cg * 4 + 2], acc.z);
        atomicAdd(&g_sumsq[cg * 4 + 3], acc.w);
    }
    __syncthreads();

    if (tid == 0) {
        __threadfence();
        int o = atomicAdd(&g_count, 1);
        if (o == AB_GRID - 1) atomicExch((int*)&g_flag, 1);
        while (g_flag == 0) __nanosleep(64);
    }
    __syncthreads();
    __threadfence();

    float4 sc, sf;
    {
        const float invN = 1.0f / (float)N_NODES;
        float4 su = __ldcg(&((const float4*)g_sum)[cg]);
        float4 sq = __ldcg(&((const float4*)g_sumsq)[cg]);
        float4 g4 = ((const float4*)gamma)[cg];
        float4 be4 = ((const float4*)beta)[cg];
        float mx = su.x * invN, my = su.y * invN, mz = su.z * invN, mw = su.w * invN;
        sc.x = g4.x * rsqrtf(sq.x * invN - mx * mx + BN_EPS);
        sc.y = g4.y * rsqrtf(sq.y * invN - my * my + BN_EPS);
        sc.z = g4.z * rsqrtf(sq.z * invN - mz * mz + BN_EPS);
        sc.w = g4.w * rsqrtf(sq.w * invN - mw * mw + BN_EPS);
        sf.x = be4.x - mx * sc.x;
        sf.y = be4.y - my * sc.y;
        sf.z = be4.z - mz * sc.z;
        sf.w = be4.w - mw * sc.w;
    }
    {
        int i = base;
        #pragma unroll
        for (int j = 0; j < AB_ITERS; j++, i += AB_STRIDE) {
            if (i < total4) {
                float4 v = vals[j];
                v.x = v.x * sc.x + sf.x;
                v.y = v.y * sc.y + sf.y;
                v.z = v.z * sc.z + sf.z;
                v.w = v.w * sc.w + sf.w;
                ((float4*)out)[i] = v;
            }
        }
    }
}

// ---------------- streams/events (created once; no device memory) ----------------
static struct SideStream {
    cudaStream_t s;
    cudaEvent_t fork_ev, join_ev;
    SideStream() {
        cudaStreamCreateWithFlags(&s, cudaStreamNonBlocking);
        cudaEventCreateWithFlags(&fork_ev, cudaEventDisableTiming);
        cudaEventCreateWithFlags(&join_ev, cudaEventDisableTiming);
        cudaFuncSetAttribute(k_gemm, cudaFuncAttributeMaxDynamicSharedMemorySize, SMEM_TOT);
    }
} g_ss;

// ---------------- launch ----------------
extern "C" void kernel_launch(void* const* d_in, const int* in_sizes, int n_in,
                              void* d_out, int out_size) {
    const float*        x     = (const float*)d_in[0];
    const unsigned int* ei    = (const unsigned int*)d_in[1];  // int32 or int64, sniffed
    const float*        W     = (const float*)d_in[2];
    const float*        bias  = (const float*)d_in[3];
    const float*        gamma = (const float*)d_in[4];
    const float*        beta  = (const float*)d_in[5];
    float*              out   = (float*)d_out;

    static bool attr_done = false;
    if (!attr_done) {   // first call is outside graph capture
        cudaFuncSetAttribute(k_gemm, cudaFuncAttributeMaxDynamicSharedMemorySize, SMEM_TOT);
        attr_done = true;
    }

    // fork: edge chain on side stream, overlapped with GEMM on main stream
    cudaEventRecord(g_ss.fork_ev, 0);
    cudaStreamWaitEvent(g_ss.s, g_ss.fork_ev, 0);

    k_init_sniff<<<(N_NODES + 255) / 256, 256, 0, g_ss.s>>>(ei);
    k_decode_deg<<<(2 * N_EDGES + 255) / 256, 256, 0, g_ss.s>>>(ei);
    k_dinv<<<(N_NODES + 255) / 256, 256, 0, g_ss.s>>>();
    cudaEventRecord(g_ss.join_ev, g_ss.s);

    k_gemm<<<(N_NODES + TILE_M - 1) / TILE_M, 256, SMEM_TOT>>>(x, W);

    // join, then scatter + fused act/bn on main stream
    cudaStreamWaitEvent(0, g_ss.join_ev, 0);
    k_scatter<<<(int)(((long long)N_EDGES * 16 + 255) / 256), 256>>>();
    k_act_bn<<<AB_GRID, 256>>>(bias, gamma, beta, out);
}